// round 8
// baseline (speedup 1.0000x reference)
#include <cuda_runtime.h>
#include <cstdint>

#define NNODE 20000
#define DDEG  16

typedef unsigned long long ull;

// ---------------- scratch (device globals; no allocations) ----------------
__device__ float g_WTih[128 * 512];      // Wih^T  [k][4H]
__device__ float g_WThh[128 * 512];      // Whh^T  [k][4H]
__device__ float g_WTself[128 * 128];    // Wself^T
__device__ float g_WTneigh[128 * 128];   // Wneigh^T
__device__ float g_Xp[(size_t)NNODE * 512];   // input projection (+bias)
__device__ float g_H[(size_t)NNODE * 128];    // LSTM final hidden
__device__ float g_h1[(size_t)NNODE * 128];   // layer-1 output

// ---------------- helpers ----------------
__device__ __forceinline__ float tanh_f(float x) {
    float y;
    asm("tanh.approx.f32 %0, %1;" : "=f"(y) : "f"(x));
    return y;
}
// sigmoid(x) = 0.5*tanh(x/2) + 0.5  (1 MUFU + 2 FMA)
__device__ __forceinline__ float sig_f(float x) {
    return fmaf(0.5f, tanh_f(0.5f * x), 0.5f);
}
__device__ __forceinline__ float sig_exact(float x) { return 1.f / (1.f + __expf(-x)); }

// Packed fp32x2 FMA (Blackwell FFMA2): d = a*b + c elementwise on 2 packed f32.
__device__ __forceinline__ ull fma2(ull a, ull b, ull c) {
    ull d;
    asm("fma.rn.f32x2 %0, %1, %2, %3;" : "=l"(d) : "l"(a), "l"(b), "l"(c));
    return d;
}
__device__ __forceinline__ ull pack2(float x, float y) {
    ull d;
    asm("mov.b64 %0, {%1, %2};" : "=l"(d) : "f"(x), "f"(y));
    return d;
}
__device__ __forceinline__ float2 unpack2(ull v) {
    float2 r;
    asm("mov.b64 {%0, %1}, %2;" : "=f"(r.x), "=f"(r.y) : "l"(v));
    return r;
}

__device__ __forceinline__ unsigned smem_u32(const void* p) {
    return (unsigned)__cvta_generic_to_shared(p);
}
__device__ __forceinline__ void cp_async16(unsigned saddr, const void* g) {
    asm volatile("cp.async.ca.shared.global [%0], [%1], 16;\n" :: "r"(saddr), "l"(g) : "memory");
}
__device__ __forceinline__ void cp_commit() { asm volatile("cp.async.commit_group;\n" ::: "memory"); }
__device__ __forceinline__ void cp_wait0()  { asm volatile("cp.async.wait_group 0;\n" ::: "memory"); }
__device__ __forceinline__ void cp_wait1()  { asm volatile("cp.async.wait_group 1;\n" ::: "memory"); }

// ---------------- transpose W[R][K] -> WT[K][R] ----------------
__global__ void transpose_kernel(const float* __restrict__ W, float* __restrict__ WT,
                                 int R, int K) {
    int i = blockIdx.x * blockDim.x + threadIdx.x;
    if (i < R * K) {
        int r = i / K, k = i - r * K;
        WT[(size_t)k * R + r] = W[i];
    }
}

// ---------------- generic fused GEMM (f32x2 inner loop) ----------------
// C[N,M] = act( A@WT + (A2?A2@WT2:0) + b1 + (b2?b2:0) ),  K=128
#define GEMM_SMEM ((64 * 132 + 128 * 68) * 4)
__global__ __launch_bounds__(256) void fused_gemm_kernel(
    const float* __restrict__ A,  const float* __restrict__ WT,
    const float* __restrict__ A2, const float* __restrict__ WT2,
    const float* __restrict__ b1, const float* __restrict__ b2,
    float* __restrict__ C, int Nrows, int M, int act)
{
    extern __shared__ float sm[];
    float* As = sm;               // [64][132] row-major
    float* Ws = sm + 64 * 132;    // [128][68] k-major
    int tid = threadIdx.x;
    int tx = tid & 15, ty = tid >> 4;
    int rowBase = blockIdx.y * 64, colBase = blockIdx.x * 64;

    ull acc[4][2];
#pragma unroll
    for (int i = 0; i < 4; i++) { acc[i][0] = 0ull; acc[i][1] = 0ull; }

    int npass = (A2 != nullptr) ? 2 : 1;
    for (int pass = 0; pass < npass; ++pass) {
        const float* Ap = pass ? A2 : A;
        const float* Wp = pass ? WT2 : WT;
        if (pass) __syncthreads();
        for (int f = tid; f < 64 * 32; f += 256) {
            int r = f >> 5, c4 = f & 31;
            float4 v = make_float4(0.f, 0.f, 0.f, 0.f);
            if (rowBase + r < Nrows)
                v = *(const float4*)(Ap + (size_t)(rowBase + r) * 128 + c4 * 4);
            *(float4*)(As + r * 132 + c4 * 4) = v;
        }
        for (int f = tid; f < 128 * 16; f += 256) {
            int k = f >> 4, c4 = f & 15;
            *(float4*)(Ws + k * 68 + c4 * 4) =
                *(const float4*)(Wp + (size_t)k * M + colBase + c4 * 4);
        }
        __syncthreads();
#pragma unroll 8
        for (int k = 0; k < 128; k++) {
            ulonglong2 w = *(const ulonglong2*)(Ws + k * 68 + tx * 4);
#pragma unroll
            for (int i = 0; i < 4; i++) {
                float a = As[(ty * 4 + i) * 132 + k];
                ull aa = pack2(a, a);
                acc[i][0] = fma2(aa, w.x, acc[i][0]);
                acc[i][1] = fma2(aa, w.y, acc[i][1]);
            }
        }
    }
#pragma unroll
    for (int i = 0; i < 4; i++) {
        int row = rowBase + ty * 4 + i;
        if (row < Nrows) {
            float2 v01 = unpack2(acc[i][0]);
            float2 v23 = unpack2(acc[i][1]);
            float vv[4] = {v01.x, v01.y, v23.x, v23.y};
#pragma unroll
            for (int j = 0; j < 4; j++) {
                int col = colBase + tx * 4 + j;
                float v = vv[j] + b1[col];
                if (b2) v += b2[col];
                if (act) v = fmaxf(v, 0.f);
                C[(size_t)row * M + col] = v;
            }
        }
    }
}

// ---------------- persistent LSTM layer ----------------
// Block: 32 nodes, 256 threads. Thread = 8 nodes (ng*8..+7) x 2 units (ug*2, +1).
// H is stored DUPLICATED in smem (each value twice, adjacent), so the (h,h)
// splat pair for fma.rn.f32x2 comes directly from an LDS.128 register quad —
// no MOV packing on the FMA pipe in the inner loop.
#define HS_STRIDE 72
#define LSTM_SMEM ((128 * HS_STRIDE + 2 * 16 * 520) * 4 + 32 * DDEG * 4)
__global__ __launch_bounds__(256, 2) void lstm_kernel(
    const float* __restrict__ Xp, const int* __restrict__ nbr,
    const float* __restrict__ WThh, float* __restrict__ Hout)
{
    extern __shared__ float sm[];
    float* Hs  = sm;                             // [128 units][HS_STRIDE] duplicated pairs
    float* Wsb = sm + 128 * HS_STRIDE;           // [2][16][520] double-buffered k-tiles
    int* idx_s = (int*)(sm + 128 * HS_STRIDE + 2 * 16 * 520);

    int tid = threadIdx.x;
    int ug = tid & 63, ng = tid >> 6;
    int u0 = ug * 2, nloc0 = ng * 8;
    int nodeBase = blockIdx.x * 32;

    for (int i = tid; i < 32 * DDEG; i += 256)
        idx_s[i] = nbr[(size_t)(nodeBase + (i >> 4)) * DDEG + (i & 15)];
    __syncthreads();

    float c0[8], c1[8];
#pragma unroll
    for (int i = 0; i < 8; i++) { c0[i] = 0.f; c1[i] = 0.f; }

    for (int t = 0; t < DDEG; ++t) {
        // --- gate init = gathered input projection (includes biases) ---
        ull aI[8], aF[8], aG[8], aO[8];
#pragma unroll
        for (int i = 0; i < 8; i++) {
            int row = idx_s[(nloc0 + i) * DDEG + t];
            const float* xr = Xp + (size_t)row * 512 + u0;
            aI[i] = *(const ull*)(xr);
            aF[i] = *(const ull*)(xr + 128);
            aG[i] = *(const ull*)(xr + 256);
            aO[i] = *(const ull*)(xr + 384);
        }
        // --- recurrent GEMM (skip at t=0: h=0) ---
        if (t > 0) {
            {   // prologue: tile 0 -> buf 0
                float* dst = Wsb;
#pragma unroll
                for (int q = 0; q < 8; q++) {
                    int f = q * 256 + tid;
                    int k = f >> 7, c4 = f & 127;
                    cp_async16(smem_u32(dst + k * 520 + c4 * 4),
                               WThh + ((size_t)k * 512 + c4 * 4));
                }
                cp_commit();
            }
            for (int kt = 0; kt < 8; ++kt) {
                if (kt + 1 < 8) {
                    float* dst = Wsb + ((kt + 1) & 1) * 16 * 520;
#pragma unroll
                    for (int q = 0; q < 8; q++) {
                        int f = q * 256 + tid;
                        int k = f >> 7, c4 = f & 127;
                        cp_async16(smem_u32(dst + k * 520 + c4 * 4),
                                   WThh + ((size_t)((kt + 1) * 16 + k) * 512 + c4 * 4));
                    }
                    cp_commit();
                    cp_wait1();
                } else {
                    cp_wait0();
                }
                __syncthreads();
                const float* W = Wsb + (kt & 1) * 16 * 520;
#pragma unroll 4
                for (int k = 0; k < 16; k++) {
                    int kk = kt * 16 + k;
                    const float* hrow = Hs + kk * HS_STRIDE + nloc0 * 2;
                    // duplicated pairs: .x/.y of each ulonglong2 is (h,h)
                    ulonglong2 hA = *(const ulonglong2*)(hrow);       // nodes 0,1
                    ulonglong2 hB = *(const ulonglong2*)(hrow + 4);   // nodes 2,3
                    ulonglong2 hC = *(const ulonglong2*)(hrow + 8);   // nodes 4,5
                    ulonglong2 hD = *(const ulonglong2*)(hrow + 12);  // nodes 6,7
                    ull wi = *(const ull*)(W + k * 520 + u0);
                    ull wf = *(const ull*)(W + k * 520 + 128 + u0);
                    ull wg = *(const ull*)(W + k * 520 + 256 + u0);
                    ull wo = *(const ull*)(W + k * 520 + 384 + u0);
#define STEPN(i, hh)                                   \
    aI[i] = fma2((hh), wi, aI[i]);                     \
    aF[i] = fma2((hh), wf, aF[i]);                     \
    aG[i] = fma2((hh), wg, aG[i]);                     \
    aO[i] = fma2((hh), wo, aO[i]);
                    STEPN(0, hA.x) STEPN(1, hA.y) STEPN(2, hB.x) STEPN(3, hB.y)
                    STEPN(4, hC.x) STEPN(5, hC.y) STEPN(6, hD.x) STEPN(7, hD.y)
#undef STEPN
                }
                __syncthreads();
            }
        }
        // --- cell update (PyTorch gate order i,f,g,o), fast approx math ---
        float hv0[8], hv1[8];
#pragma unroll
        for (int i = 0; i < 8; i++) {
            float2 vi = unpack2(aI[i]);
            float2 vf = unpack2(aF[i]);
            float2 vg = unpack2(aG[i]);
            float2 vo = unpack2(aO[i]);
            c0[i]  = sig_f(vf.x) * c0[i] + sig_f(vi.x) * tanh_f(vg.x);
            hv0[i] = sig_f(vo.x) * tanh_f(c0[i]);
            c1[i]  = sig_f(vf.y) * c1[i] + sig_f(vi.y) * tanh_f(vg.y);
            hv1[i] = sig_f(vo.y) * tanh_f(c1[i]);
        }
        if (t < DDEG - 1) {
            float* r0 = Hs + u0 * HS_STRIDE + nloc0 * 2;
            float* r1 = Hs + (u0 + 1) * HS_STRIDE + nloc0 * 2;
#pragma unroll
            for (int i = 0; i < 8; i += 2) {
                *(float4*)(r0 + i * 2) = make_float4(hv0[i], hv0[i], hv0[i + 1], hv0[i + 1]);
                *(float4*)(r1 + i * 2) = make_float4(hv1[i], hv1[i], hv1[i + 1], hv1[i + 1]);
            }
            __syncthreads();
        } else {
#pragma unroll
            for (int i = 0; i < 8; i++) {
                int n = nodeBase + nloc0 + i;
                *(float2*)(Hout + (size_t)n * 128 + u0) = make_float2(hv0[i], hv1[i]);
            }
        }
    }
}

// ---------------- final layer-2 combine: OUT=1 + sigmoid ----------------
__global__ void out_kernel(const float* __restrict__ h1, const float* __restrict__ H,
                           const float* __restrict__ Wself, const float* __restrict__ Wneigh,
                           const float* __restrict__ b, float* __restrict__ out, int Nrows)
{
    int gwarp = (blockIdx.x * blockDim.x + threadIdx.x) >> 5;
    int lane = threadIdx.x & 31;
    if (gwarp >= Nrows) return;
    float s = 0.f;
#pragma unroll
    for (int q = 0; q < 4; q++) {
        int k = lane + 32 * q;
        s += h1[(size_t)gwarp * 128 + k] * Wself[k] + H[(size_t)gwarp * 128 + k] * Wneigh[k];
    }
#pragma unroll
    for (int off = 16; off; off >>= 1) s += __shfl_xor_sync(0xFFFFFFFFu, s, off);
    if (lane == 0) out[gwarp] = sig_exact(s + b[0]);
}

// ---------------- launch ----------------
extern "C" void kernel_launch(void* const* d_in, const int* in_sizes, int n_in,
                              void* d_out, int out_size)
{
    const float* x       = (const float*)d_in[0];
    const int*   nbr     = (const int*)d_in[1];
    const float* Wih1    = (const float*)d_in[2];
    const float* Whh1    = (const float*)d_in[3];
    const float* bih1    = (const float*)d_in[4];
    const float* bhh1    = (const float*)d_in[5];
    const float* Wself1  = (const float*)d_in[6];
    const float* Wneigh1 = (const float*)d_in[7];
    const float* bneigh1 = (const float*)d_in[8];
    const float* Wih2    = (const float*)d_in[9];
    const float* Whh2    = (const float*)d_in[10];
    const float* bih2    = (const float*)d_in[11];
    const float* bhh2    = (const float*)d_in[12];
    const float* Wself2  = (const float*)d_in[13];
    const float* Wneigh2 = (const float*)d_in[14];
    const float* bneigh2 = (const float*)d_in[15];
    float* out = (float*)d_out;

    float *WTih, *WThh, *WTself, *WTneigh, *Xp, *H, *h1;
    cudaGetSymbolAddress((void**)&WTih,    g_WTih);
    cudaGetSymbolAddress((void**)&WThh,    g_WThh);
    cudaGetSymbolAddress((void**)&WTself,  g_WTself);
    cudaGetSymbolAddress((void**)&WTneigh, g_WTneigh);
    cudaGetSymbolAddress((void**)&Xp,      g_Xp);
    cudaGetSymbolAddress((void**)&H,       g_H);
    cudaGetSymbolAddress((void**)&h1,      g_h1);

    cudaFuncSetAttribute(fused_gemm_kernel, cudaFuncAttributeMaxDynamicSharedMemorySize, GEMM_SMEM);
    cudaFuncSetAttribute(lstm_kernel,       cudaFuncAttributeMaxDynamicSharedMemorySize, LSTM_SMEM);

    const int TB = 256;
    // ---- layer 1 ----
    transpose_kernel<<<(512 * 128 + TB - 1) / TB, TB>>>(Wih1,    WTih,    512, 128);
    transpose_kernel<<<(512 * 128 + TB - 1) / TB, TB>>>(Whh1,    WThh,    512, 128);
    transpose_kernel<<<(128 * 128 + TB - 1) / TB, TB>>>(Wself1,  WTself,  128, 128);
    transpose_kernel<<<(128 * 128 + TB - 1) / TB, TB>>>(Wneigh1, WTneigh, 128, 128);

    fused_gemm_kernel<<<dim3(8, 313), TB, GEMM_SMEM>>>(
        x, WTih, nullptr, nullptr, bih1, bhh1, Xp, NNODE, 512, 0);
    lstm_kernel<<<NNODE / 32, TB, LSTM_SMEM>>>(Xp, nbr, WThh, H);
    fused_gemm_kernel<<<dim3(2, 313), TB, GEMM_SMEM>>>(
        x, WTself, H, WTneigh, bneigh1, nullptr, h1, NNODE, 128, 1);

    // ---- layer 2 ----
    transpose_kernel<<<(512 * 128 + TB - 1) / TB, TB>>>(Wih2, WTih, 512, 128);
    transpose_kernel<<<(512 * 128 + TB - 1) / TB, TB>>>(Whh2, WThh, 512, 128);

    fused_gemm_kernel<<<dim3(8, 313), TB, GEMM_SMEM>>>(
        h1, WTih, nullptr, nullptr, bih2, bhh2, Xp, NNODE, 512, 0);
    lstm_kernel<<<NNODE / 32, TB, LSTM_SMEM>>>(Xp, nbr, WThh, H);
    out_kernel<<<(NNODE * 32 + TB - 1) / TB, TB>>>(h1, H, Wself2, Wneigh2, bneigh2, out, NNODE);
}

// round 9
// speedup vs baseline: 1.2604x; 1.2604x over previous
#include <cuda_runtime.h>
#include <cstdint>

#define NNODE 20000
#define DDEG  16

typedef unsigned long long ull;

// ---------------- scratch (device globals; no allocations) ----------------
__device__ float g_WTih[128 * 512];      // Wih^T  [k][4H]
__device__ float g_WThh[128 * 512];      // Whh^T  [k][4H]
__device__ float g_WTself[128 * 128];    // Wself^T
__device__ float g_WTneigh[128 * 128];   // Wneigh^T
__device__ float g_Xp[(size_t)NNODE * 512];   // input projection (+bias)
__device__ float g_H[(size_t)NNODE * 128];    // LSTM final hidden
__device__ float g_h1[(size_t)NNODE * 128];   // layer-1 output

// ---------------- helpers ----------------
__device__ __forceinline__ float tanh_f(float x) {
    float y;
    asm("tanh.approx.f32 %0, %1;" : "=f"(y) : "f"(x));
    return y;
}
// sigmoid(x) = 0.5*tanh(x/2) + 0.5  (1 MUFU + 2 FMA)
__device__ __forceinline__ float sig_f(float x) {
    return fmaf(0.5f, tanh_f(0.5f * x), 0.5f);
}
__device__ __forceinline__ float sig_exact(float x) { return 1.f / (1.f + __expf(-x)); }

// Packed fp32x2 FMA (Blackwell FFMA2): d = a*b + c elementwise on 2 packed f32.
__device__ __forceinline__ ull fma2(ull a, ull b, ull c) {
    ull d;
    asm("fma.rn.f32x2 %0, %1, %2, %3;" : "=l"(d) : "l"(a), "l"(b), "l"(c));
    return d;
}
__device__ __forceinline__ ull pack2(float x, float y) {
    ull d;
    asm("mov.b64 %0, {%1, %2};" : "=l"(d) : "f"(x), "f"(y));
    return d;
}
__device__ __forceinline__ float2 unpack2(ull v) {
    float2 r;
    asm("mov.b64 {%0, %1}, %2;" : "=f"(r.x), "=f"(r.y) : "l"(v));
    return r;
}

__device__ __forceinline__ unsigned smem_u32(const void* p) {
    return (unsigned)__cvta_generic_to_shared(p);
}
__device__ __forceinline__ void cp_async16(unsigned saddr, const void* g) {
    asm volatile("cp.async.ca.shared.global [%0], [%1], 16;\n" :: "r"(saddr), "l"(g) : "memory");
}
__device__ __forceinline__ void cp_commit() { asm volatile("cp.async.commit_group;\n" ::: "memory"); }
__device__ __forceinline__ void cp_wait0()  { asm volatile("cp.async.wait_group 0;\n" ::: "memory"); }

// ---------------- transpose W[R][K] -> WT[K][R] ----------------
__global__ void transpose_kernel(const float* __restrict__ W, float* __restrict__ WT,
                                 int R, int K) {
    int i = blockIdx.x * blockDim.x + threadIdx.x;
    if (i < R * K) {
        int r = i / K, k = i - r * K;
        WT[(size_t)k * R + r] = W[i];
    }
}

// ---------------- generic fused GEMM (f32x2 inner loop) ----------------
// C[N,M] = act( A@WT + (A2?A2@WT2:0) + b1 + (b2?b2:0) ),  K=128
#define GEMM_SMEM ((64 * 132 + 128 * 68) * 4)
__global__ __launch_bounds__(256) void fused_gemm_kernel(
    const float* __restrict__ A,  const float* __restrict__ WT,
    const float* __restrict__ A2, const float* __restrict__ WT2,
    const float* __restrict__ b1, const float* __restrict__ b2,
    float* __restrict__ C, int Nrows, int M, int act)
{
    extern __shared__ float sm[];
    float* As = sm;               // [64][132] row-major
    float* Ws = sm + 64 * 132;    // [128][68] k-major
    int tid = threadIdx.x;
    int tx = tid & 15, ty = tid >> 4;
    int rowBase = blockIdx.y * 64, colBase = blockIdx.x * 64;

    ull acc[4][2];
#pragma unroll
    for (int i = 0; i < 4; i++) { acc[i][0] = 0ull; acc[i][1] = 0ull; }

    int npass = (A2 != nullptr) ? 2 : 1;
    for (int pass = 0; pass < npass; ++pass) {
        const float* Ap = pass ? A2 : A;
        const float* Wp = pass ? WT2 : WT;
        if (pass) __syncthreads();
        for (int f = tid; f < 64 * 32; f += 256) {
            int r = f >> 5, c4 = f & 31;
            float4 v = make_float4(0.f, 0.f, 0.f, 0.f);
            if (rowBase + r < Nrows)
                v = *(const float4*)(Ap + (size_t)(rowBase + r) * 128 + c4 * 4);
            *(float4*)(As + r * 132 + c4 * 4) = v;
        }
        for (int f = tid; f < 128 * 16; f += 256) {
            int k = f >> 4, c4 = f & 15;
            *(float4*)(Ws + k * 68 + c4 * 4) =
                *(const float4*)(Wp + (size_t)k * M + colBase + c4 * 4);
        }
        __syncthreads();
#pragma unroll 8
        for (int k = 0; k < 128; k++) {
            ulonglong2 w = *(const ulonglong2*)(Ws + k * 68 + tx * 4);
#pragma unroll
            for (int i = 0; i < 4; i++) {
                float a = As[(ty * 4 + i) * 132 + k];
                ull aa = pack2(a, a);
                acc[i][0] = fma2(aa, w.x, acc[i][0]);
                acc[i][1] = fma2(aa, w.y, acc[i][1]);
            }
        }
    }
#pragma unroll
    for (int i = 0; i < 4; i++) {
        int row = rowBase + ty * 4 + i;
        if (row < Nrows) {
            float2 v01 = unpack2(acc[i][0]);
            float2 v23 = unpack2(acc[i][1]);
            float vv[4] = {v01.x, v01.y, v23.x, v23.y};
#pragma unroll
            for (int j = 0; j < 4; j++) {
                int col = colBase + tx * 4 + j;
                float v = vv[j] + b1[col];
                if (b2) v += b2[col];
                if (act) v = fmaxf(v, 0.f);
                C[(size_t)row * M + col] = v;
            }
        }
    }
}

// ---------------- persistent LSTM layer ----------------
// Block: 32 nodes, 256 threads. Thread = 8 nodes (ng*8..+7) x 2 units (ug*2, +1).
// R5 inner loop (f32x2 with h-splat packs) + MUFU epilogue + 1 barrier per kt.
#define LSTM_SMEM (128 * 36 * 4 + 2 * 16 * 520 * 4 + 32 * DDEG * 4)
__global__ __launch_bounds__(256, 2) void lstm_kernel(
    const float* __restrict__ Xp, const int* __restrict__ nbr,
    const float* __restrict__ WThh, float* __restrict__ Hout)
{
    extern __shared__ float sm[];
    float* Hs  = sm;                        // [128 units][36] (32 nodes + pad)
    float* Wsb = sm + 128 * 36;             // [2][16][520] double-buffered k-tiles
    int* idx_s = (int*)(sm + 128 * 36 + 2 * 16 * 520);

    int tid = threadIdx.x;
    int ug = tid & 63, ng = tid >> 6;
    int u0 = ug * 2, nloc0 = ng * 8;
    int nodeBase = blockIdx.x * 32;

    for (int i = tid; i < 32 * DDEG; i += 256)
        idx_s[i] = nbr[(size_t)(nodeBase + (i >> 4)) * DDEG + (i & 15)];
    __syncthreads();

    float c0[8], c1[8];
#pragma unroll
    for (int i = 0; i < 8; i++) { c0[i] = 0.f; c1[i] = 0.f; }

    for (int t = 0; t < DDEG; ++t) {
        // --- gate init = gathered input projection (includes biases) ---
        ull aI[8], aF[8], aG[8], aO[8];
#pragma unroll
        for (int i = 0; i < 8; i++) {
            int row = idx_s[(nloc0 + i) * DDEG + t];
            const float* xr = Xp + (size_t)row * 512 + u0;
            aI[i] = *(const ull*)(xr);
            aF[i] = *(const ull*)(xr + 128);
            aG[i] = *(const ull*)(xr + 256);
            aO[i] = *(const ull*)(xr + 384);
        }
        // --- recurrent GEMM (skip at t=0: h=0) ---
        if (t > 0) {
            {   // prologue: tile 0 -> buf 0
                float* dst = Wsb;
#pragma unroll
                for (int q = 0; q < 8; q++) {
                    int f = q * 256 + tid;
                    int k = f >> 7, c4 = f & 127;
                    cp_async16(smem_u32(dst + k * 520 + c4 * 4),
                               WThh + ((size_t)k * 512 + c4 * 4));
                }
                cp_commit();
            }
            for (int kt = 0; kt < 8; ++kt) {
                // my slice of tile kt has arrived
                cp_wait0();
                // single barrier: (a) everyone's slice of tile kt visible,
                // (b) everyone finished computing tile kt-1 (so its buffer is free)
                __syncthreads();
                if (kt + 1 < 8) {
                    float* dst = Wsb + ((kt + 1) & 1) * 16 * 520;
#pragma unroll
                    for (int q = 0; q < 8; q++) {
                        int f = q * 256 + tid;
                        int k = f >> 7, c4 = f & 127;
                        cp_async16(smem_u32(dst + k * 520 + c4 * 4),
                                   WThh + ((size_t)((kt + 1) * 16 + k) * 512 + c4 * 4));
                    }
                    cp_commit();
                }
                const float* W = Wsb + (kt & 1) * 16 * 520;
#pragma unroll 4
                for (int k = 0; k < 16; k++) {
                    int kk = kt * 16 + k;
                    float4 hA = *(const float4*)(Hs + kk * 36 + nloc0);
                    float4 hB = *(const float4*)(Hs + kk * 36 + nloc0 + 4);
                    ull wi = *(const ull*)(W + k * 520 + u0);
                    ull wf = *(const ull*)(W + k * 520 + 128 + u0);
                    ull wg = *(const ull*)(W + k * 520 + 256 + u0);
                    ull wo = *(const ull*)(W + k * 520 + 384 + u0);
#define STEPN(i, hv)                                   \
    {                                                  \
        ull hh = pack2((hv), (hv));                    \
        aI[i] = fma2(hh, wi, aI[i]);                   \
        aF[i] = fma2(hh, wf, aF[i]);                   \
        aG[i] = fma2(hh, wg, aG[i]);                   \
        aO[i] = fma2(hh, wo, aO[i]);                   \
    }
                    STEPN(0, hA.x) STEPN(1, hA.y) STEPN(2, hA.z) STEPN(3, hA.w)
                    STEPN(4, hB.x) STEPN(5, hB.y) STEPN(6, hB.z) STEPN(7, hB.w)
#undef STEPN
                }
            }
            // make sure all warps finished reading Hs (tile 7) before overwrite
            __syncthreads();
        }
        // --- cell update (PyTorch gate order i,f,g,o), MUFU approx math ---
        float hv0[8], hv1[8];
#pragma unroll
        for (int i = 0; i < 8; i++) {
            float2 vi = unpack2(aI[i]);
            float2 vf = unpack2(aF[i]);
            float2 vg = unpack2(aG[i]);
            float2 vo = unpack2(aO[i]);
            c0[i]  = sig_f(vf.x) * c0[i] + sig_f(vi.x) * tanh_f(vg.x);
            hv0[i] = sig_f(vo.x) * tanh_f(c0[i]);
            c1[i]  = sig_f(vf.y) * c1[i] + sig_f(vi.y) * tanh_f(vg.y);
            hv1[i] = sig_f(vo.y) * tanh_f(c1[i]);
        }
        if (t < DDEG - 1) {
            *(float4*)(Hs + u0 * 36 + nloc0)           = make_float4(hv0[0], hv0[1], hv0[2], hv0[3]);
            *(float4*)(Hs + u0 * 36 + nloc0 + 4)       = make_float4(hv0[4], hv0[5], hv0[6], hv0[7]);
            *(float4*)(Hs + (u0 + 1) * 36 + nloc0)     = make_float4(hv1[0], hv1[1], hv1[2], hv1[3]);
            *(float4*)(Hs + (u0 + 1) * 36 + nloc0 + 4) = make_float4(hv1[4], hv1[5], hv1[6], hv1[7]);
            __syncthreads();
        } else {
#pragma unroll
            for (int i = 0; i < 8; i++) {
                int n = nodeBase + nloc0 + i;
                *(float2*)(Hout + (size_t)n * 128 + u0) = make_float2(hv0[i], hv1[i]);
            }
        }
    }
}

// ---------------- final layer-2 combine: OUT=1 + sigmoid ----------------
__global__ void out_kernel(const float* __restrict__ h1, const float* __restrict__ H,
                           const float* __restrict__ Wself, const float* __restrict__ Wneigh,
                           const float* __restrict__ b, float* __restrict__ out, int Nrows)
{
    int gwarp = (blockIdx.x * blockDim.x + threadIdx.x) >> 5;
    int lane = threadIdx.x & 31;
    if (gwarp >= Nrows) return;
    float s = 0.f;
#pragma unroll
    for (int q = 0; q < 4; q++) {
        int k = lane + 32 * q;
        s += h1[(size_t)gwarp * 128 + k] * Wself[k] + H[(size_t)gwarp * 128 + k] * Wneigh[k];
    }
#pragma unroll
    for (int off = 16; off; off >>= 1) s += __shfl_xor_sync(0xFFFFFFFFu, s, off);
    if (lane == 0) out[gwarp] = sig_exact(s + b[0]);
}

// ---------------- launch ----------------
extern "C" void kernel_launch(void* const* d_in, const int* in_sizes, int n_in,
                              void* d_out, int out_size)
{
    const float* x       = (const float*)d_in[0];
    const int*   nbr     = (const int*)d_in[1];
    const float* Wih1    = (const float*)d_in[2];
    const float* Whh1    = (const float*)d_in[3];
    const float* bih1    = (const float*)d_in[4];
    const float* bhh1    = (const float*)d_in[5];
    const float* Wself1  = (const float*)d_in[6];
    const float* Wneigh1 = (const float*)d_in[7];
    const float* bneigh1 = (const float*)d_in[8];
    const float* Wih2    = (const float*)d_in[9];
    const float* Whh2    = (const float*)d_in[10];
    const float* bih2    = (const float*)d_in[11];
    const float* bhh2    = (const float*)d_in[12];
    const float* Wself2  = (const float*)d_in[13];
    const float* Wneigh2 = (const float*)d_in[14];
    const float* bneigh2 = (const float*)d_in[15];
    float* out = (float*)d_out;

    float *WTih, *WThh, *WTself, *WTneigh, *Xp, *H, *h1;
    cudaGetSymbolAddress((void**)&WTih,    g_WTih);
    cudaGetSymbolAddress((void**)&WThh,    g_WThh);
    cudaGetSymbolAddress((void**)&WTself,  g_WTself);
    cudaGetSymbolAddress((void**)&WTneigh, g_WTneigh);
    cudaGetSymbolAddress((void**)&Xp,      g_Xp);
    cudaGetSymbolAddress((void**)&H,       g_H);
    cudaGetSymbolAddress((void**)&h1,      g_h1);

    cudaFuncSetAttribute(fused_gemm_kernel, cudaFuncAttributeMaxDynamicSharedMemorySize, GEMM_SMEM);
    cudaFuncSetAttribute(lstm_kernel,       cudaFuncAttributeMaxDynamicSharedMemorySize, LSTM_SMEM);

    const int TB = 256;
    // ---- layer 1 ----
    transpose_kernel<<<(512 * 128 + TB - 1) / TB, TB>>>(Wih1,    WTih,    512, 128);
    transpose_kernel<<<(512 * 128 + TB - 1) / TB, TB>>>(Whh1,    WThh,    512, 128);
    transpose_kernel<<<(128 * 128 + TB - 1) / TB, TB>>>(Wself1,  WTself,  128, 128);
    transpose_kernel<<<(128 * 128 + TB - 1) / TB, TB>>>(Wneigh1, WTneigh, 128, 128);

    fused_gemm_kernel<<<dim3(8, 313), TB, GEMM_SMEM>>>(
        x, WTih, nullptr, nullptr, bih1, bhh1, Xp, NNODE, 512, 0);
    lstm_kernel<<<NNODE / 32, TB, LSTM_SMEM>>>(Xp, nbr, WThh, H);
    fused_gemm_kernel<<<dim3(2, 313), TB, GEMM_SMEM>>>(
        x, WTself, H, WTneigh, bneigh1, nullptr, h1, NNODE, 128, 1);

    // ---- layer 2 ----
    transpose_kernel<<<(512 * 128 + TB - 1) / TB, TB>>>(Wih2, WTih, 512, 128);
    transpose_kernel<<<(512 * 128 + TB - 1) / TB, TB>>>(Whh2, WThh, 512, 128);

    fused_gemm_kernel<<<dim3(8, 313), TB, GEMM_SMEM>>>(
        h1, WTih, nullptr, nullptr, bih2, bhh2, Xp, NNODE, 512, 0);
    lstm_kernel<<<NNODE / 32, TB, LSTM_SMEM>>>(Xp, nbr, WThh, H);
    out_kernel<<<(NNODE * 32 + TB - 1) / TB, TB>>>(h1, H, Wself2, Wneigh2, bneigh2, out, NNODE);
}